// round 16
// baseline (speedup 1.0000x reference)
#include <cuda_runtime.h>

// Shapes (compile-time constants from the reference)
constexpr int B  = 2;
constexpr int L  = 24;
constexpr int R  = 8;
constexpr int C  = 32;
constexpr int H  = 48;
constexpr int WF = 49;

constexpr int RCW  = R * C * WF;        // 12,544   (A elements per (b,l))
constexpr int HW   = H * WF;            // 2,352
constexpr int RCHW = R * C * H * WF;    // 602,112  (u elements per (b,l))
constexpr int NA   = B * L * RCW;       // 602,112  (total A elements)
constexpr int NU   = B * L * RCHW;      // 28,901,376 (u elements per array)

// Precomputed transition coefficients A = decay * (cos, sin), interleaved
// float2. 4.8 MB -> L2-resident during the scan kernel. In-loop A LDGs stay
// GLOBAL: every alternative (smem R6/R8, cp.async R12, reg-cap R13) lost.
__device__ float2 g_A[NA];

// ---------------------------------------------------------------------------
// Kernel 1: A[b,l,r,c,w] = exp(-nu*dt) * (cos(th*dt), sin(th*dt))
// Vectorized: 4 elements/thread (NA % 4 == 0), float4 in, 2x float4 out.
// A 4-element chunk never crosses a (b,l) row (RCW ... 12544 % 4 == 0), so
// one dt lookup per thread. Fast-math: measured rel_err 2.5e-7 vs 1e-3.
// ---------------------------------------------------------------------------
__global__ void compute_A_kernel(const float4* __restrict__ nu_rate,
                                 const float4* __restrict__ theta_rate,
                                 const float*  __restrict__ dt_seq) {
    int i4 = blockIdx.x * blockDim.x + threadIdx.x;   // float4 index
    if (i4 >= NA / 4) return;
    float dt = dt_seq[(i4 * 4) / RCW];
    const float4 nu = nu_rate[i4];
    const float4 th = theta_rate[i4];

    float4 lo, hi;   // interleaved (cos,sin) pairs
    float s, c;
    lo.x = __expf(-nu.x * dt); __sincosf(th.x * dt, &s, &c);
    lo.y = lo.x * s; lo.x = lo.x * c;
    lo.z = __expf(-nu.y * dt); __sincosf(th.y * dt, &s, &c);
    lo.w = lo.z * s; lo.z = lo.z * c;
    hi.x = __expf(-nu.z * dt); __sincosf(th.z * dt, &s, &c);
    hi.y = hi.x * s; hi.x = hi.x * c;
    hi.z = __expf(-nu.w * dt); __sincosf(th.w * dt, &s, &c);
    hi.w = hi.z * s; hi.z = hi.z * c;

    float4* dst = reinterpret_cast<float4*>(&g_A[i4 * 4]);
    dst[0] = lo;
    dst[1] = hi;
    cudaTriggerProgrammaticLaunchCompletion();
}

// ---------------------------------------------------------------------------
// Kernel 2: R9 scan with ONE structural change: TWO l-steps per unrolled
// iteration, all four u float4 loads issued up front. Doubles front-batched
// DRAM MLP (MLP_p1 2 -> 4) for +8 live regs (~62), staying under the
// 64-reg / 4-CTA boundary — occupancy and wave structure unchanged
// (the horizontal version R10/R11 paid 80 regs / 3 CTAs and lost).
// ---------------------------------------------------------------------------
__global__ void __launch_bounds__(256, 4)
scan_kernel(const float4* __restrict__ ur,
            const float4* __restrict__ ui,
            float4* __restrict__ out) {
    int t = blockIdx.x * blockDim.x + threadIdx.x;   // 0 .. 301,055
    int base = t * 4;                                 // global element index
    int b    = base / RCHW;                           // batch
    int flat = base - b * RCHW;                       // channel within batch

    // A index per lane: a_flat = (e/HW)*WF + (e%WF); constant across l.
    int aidx0, aidx1, aidx2, aidx3;
    {
        int e0 = flat;
        aidx0 = (e0 / HW) * WF + (e0 % WF);
        int e1 = flat + 1;
        aidx1 = (e1 / HW) * WF + (e1 % WF);
        int e2 = flat + 2;
        aidx2 = (e2 / HW) * WF + (e2 % WF);
        int e3 = flat + 3;
        aidx3 = (e3 / HW) * WF + (e3 % WF);
    }

    // Wait for compute_A's g_A writes (PDL; measured cost: none).
    cudaGridDependencySynchronize();

    float hr0 = 0.f, hi0 = 0.f, hr1 = 0.f, hi1 = 0.f;
    float hr2 = 0.f, hi2 = 0.f, hr3 = 0.f, hi3 = 0.f;

    const int bL = b * L;
    const int flat4 = flat >> 2;

    #pragma unroll
    for (int l = 0; l < L; l += 2) {
        const int uoffa = (bL + l    ) * (RCHW >> 2) + flat4;
        const int uoffb = (bL + l + 1) * (RCHW >> 2) + flat4;
        // Front-batch all four DRAM loads for the two steps.
        const float4 vra = __ldcs(&ur[uoffa]);
        const float4 via = __ldcs(&ui[uoffa]);
        const float4 vrb = __ldcs(&ur[uoffb]);
        const float4 vib = __ldcs(&ui[uoffb]);

        // ---- step l ----
        {
            const int aoff = (bL + l) * RCW;
            const float2 A0 = g_A[aoff + aidx0];
            const float2 A1 = g_A[aoff + aidx1];
            const float2 A2 = g_A[aoff + aidx2];
            const float2 A3 = g_A[aoff + aidx3];

            float nr, ni;
            nr = A0.x * hr0 - A0.y * hi0 + vra.x;
            ni = A0.x * hi0 + A0.y * hr0 + via.x;
            hr0 = nr; hi0 = ni;
            nr = A1.x * hr1 - A1.y * hi1 + vra.y;
            ni = A1.x * hi1 + A1.y * hr1 + via.y;
            hr1 = nr; hi1 = ni;
            nr = A2.x * hr2 - A2.y * hi2 + vra.z;
            ni = A2.x * hi2 + A2.y * hr2 + via.z;
            hr2 = nr; hi2 = ni;
            nr = A3.x * hr3 - A3.y * hi3 + vra.w;
            ni = A3.x * hi3 + A3.y * hr3 + via.w;
            hr3 = nr; hi3 = ni;

            __stcs(&out[uoffa],             make_float4(hr0, hr1, hr2, hr3));
            __stcs(&out[(NU >> 2) + uoffa], make_float4(hi0, hi1, hi2, hi3));
        }

        // ---- step l+1 ----
        {
            const int aoff = (bL + l + 1) * RCW;
            const float2 A0 = g_A[aoff + aidx0];
            const float2 A1 = g_A[aoff + aidx1];
            const float2 A2 = g_A[aoff + aidx2];
            const float2 A3 = g_A[aoff + aidx3];

            float nr, ni;
            nr = A0.x * hr0 - A0.y * hi0 + vrb.x;
            ni = A0.x * hi0 + A0.y * hr0 + vib.x;
            hr0 = nr; hi0 = ni;
            nr = A1.x * hr1 - A1.y * hi1 + vrb.y;
            ni = A1.x * hi1 + A1.y * hr1 + vib.y;
            hr1 = nr; hi1 = ni;
            nr = A2.x * hr2 - A2.y * hi2 + vrb.z;
            ni = A2.x * hi2 + A2.y * hr2 + vib.z;
            hr2 = nr; hi2 = ni;
            nr = A3.x * hr3 - A3.y * hi3 + vrb.w;
            ni = A3.x * hi3 + A3.y * hr3 + vib.w;
            hr3 = nr; hi3 = ni;

            __stcs(&out[uoffb],             make_float4(hr0, hr1, hr2, hr3));
            __stcs(&out[(NU >> 2) + uoffb], make_float4(hi0, hi1, hi2, hi3));
        }
    }
}

// ---------------------------------------------------------------------------
// kernel_launch: two launches (scan via PDL), graph-capturable, no allocs.
// Inputs (metadata order): nu_rate, theta_rate, dt_seq, u_real, u_imag.
// ---------------------------------------------------------------------------
extern "C" void kernel_launch(void* const* d_in, const int* in_sizes, int n_in,
                              void* d_out, int out_size) {
    const float4* nu = (const float4*)d_in[0];
    const float4* th = (const float4*)d_in[1];
    const float*  dt = (const float*)d_in[2];
    const float4* ur = (const float4*)d_in[3];
    const float4* ui = (const float4*)d_in[4];
    float4* out = (float4*)d_out;

    compute_A_kernel<<<(NA / 4 + 255) / 256, 256>>>(nu, th, dt);

    constexpr int nthreads = (B * RCHW) / 4;   // 301,056
    cudaLaunchConfig_t cfg = {};
    cfg.gridDim  = dim3(nthreads / 256);       // 1176
    cfg.blockDim = dim3(256);
    cfg.stream   = 0;
    cudaLaunchAttribute attrs[1];
    attrs[0].id = cudaLaunchAttributeProgrammaticStreamSerialization;
    attrs[0].val.programmaticStreamSerializationAllowed = 1;
    cfg.attrs    = attrs;
    cfg.numAttrs = 1;
    cudaLaunchKernelEx(&cfg, scan_kernel, ur, ui, out);
}

// round 17
// speedup vs baseline: 1.0073x; 1.0073x over previous
#include <cuda_runtime.h>

// Shapes (compile-time constants from the reference)
constexpr int B  = 2;
constexpr int L  = 24;
constexpr int R  = 8;
constexpr int C  = 32;
constexpr int H  = 48;
constexpr int WF = 49;

constexpr int RCW  = R * C * WF;        // 12,544   (A elements per (b,l))
constexpr int HW   = H * WF;            // 2,352
constexpr int RCHW = R * C * H * WF;    // 602,112  (u elements per (b,l))
constexpr int NA   = B * L * RCW;       // 602,112  (total A elements)
constexpr int NU   = B * L * RCHW;      // 28,901,376 (u elements per array)

// Precomputed transition coefficients A = decay * (cos, sin), interleaved
// float2. 4.8 MB -> L2-resident during the scan kernel. In-loop A LDGs stay
// GLOBAL: every alternative (smem R6/R8, cp.async R12, reg-cap R13, pairing
// R16) measured worse or neutral. R9's 54-reg natural compile is the optimum.
__device__ float2 g_A[NA];

// ---------------------------------------------------------------------------
// Kernel 1: A[b,l,r,c,w] = exp(-nu*dt) * (cos(th*dt), sin(th*dt))
// Vectorized: 4 elements/thread (RCW % 4 == 0 -> chunk never crosses a
// (b,l) row; one dt lookup). Measured component win: -1.8us vs scalar.
// Fast-math: measured rel_err 2.5e-7 vs 1e-3 threshold.
// ---------------------------------------------------------------------------
__global__ void compute_A_kernel(const float4* __restrict__ nu_rate,
                                 const float4* __restrict__ theta_rate,
                                 const float*  __restrict__ dt_seq) {
    int i4 = blockIdx.x * blockDim.x + threadIdx.x;   // float4 index
    if (i4 >= NA / 4) return;
    float dt = dt_seq[(i4 * 4) / RCW];
    const float4 nu = nu_rate[i4];
    const float4 th = theta_rate[i4];

    float4 lo, hi;   // interleaved (cos,sin) pairs
    float s, c;
    lo.x = __expf(-nu.x * dt); __sincosf(th.x * dt, &s, &c);
    lo.y = lo.x * s; lo.x = lo.x * c;
    lo.z = __expf(-nu.y * dt); __sincosf(th.y * dt, &s, &c);
    lo.w = lo.z * s; lo.z = lo.z * c;
    hi.x = __expf(-nu.z * dt); __sincosf(th.z * dt, &s, &c);
    hi.y = hi.x * s; hi.x = hi.x * c;
    hi.z = __expf(-nu.w * dt); __sincosf(th.w * dt, &s, &c);
    hi.w = hi.z * s; hi.z = hi.z * c;

    float4* dst = reinterpret_cast<float4*>(&g_A[i4 * 4]);
    dst[0] = lo;
    dst[1] = hi;
    cudaTriggerProgrammaticLaunchCompletion();
}

// ---------------------------------------------------------------------------
// Kernel 2: the R9 scan body byte-exact (measured 70.46/70.50us, 54 regs,
// DRAM 72%): 4 consecutive channels/thread, float4 __ldcs u loads, in-loop
// LDG.64 A loads from L2-resident g_A, float4 __stcs stores. Plus the PDL
// grid sync (measured zero cost) so launch overlaps compute_A.
// ---------------------------------------------------------------------------
__global__ void __launch_bounds__(256, 4)
scan_kernel(const float4* __restrict__ ur,
            const float4* __restrict__ ui,
            float4* __restrict__ out) {
    int t = blockIdx.x * blockDim.x + threadIdx.x;   // 0 .. 301,055
    int base = t * 4;                                 // global element index
    int b    = base / RCHW;                           // batch
    int flat = base - b * RCHW;                       // channel within batch

    // A index per lane: a_flat = (e/HW)*WF + (e%WF); constant across l
    // (stride RCW per step), so compute once.
    int aidx0, aidx1, aidx2, aidx3;
    {
        int e0 = flat;
        aidx0 = (e0 / HW) * WF + (e0 % WF);
        int e1 = flat + 1;
        aidx1 = (e1 / HW) * WF + (e1 % WF);
        int e2 = flat + 2;
        aidx2 = (e2 / HW) * WF + (e2 % WF);
        int e3 = flat + 3;
        aidx3 = (e3 / HW) * WF + (e3 % WF);
    }

    // Wait for compute_A's g_A writes (PDL; measured cost: none).
    cudaGridDependencySynchronize();

    float hr0 = 0.f, hi0 = 0.f, hr1 = 0.f, hi1 = 0.f;
    float hr2 = 0.f, hi2 = 0.f, hr3 = 0.f, hi3 = 0.f;

    const int bL = b * L;
    const int flat4 = flat >> 2;

    #pragma unroll
    for (int l = 0; l < L; ++l) {
        const int uoff4 = (bL + l) * (RCHW >> 2) + flat4;  // float4 index
        const float4 vr = __ldcs(&ur[uoff4]);   // read-once: evict-first
        const float4 vi = __ldcs(&ui[uoff4]);

        const int aoff = (bL + l) * RCW;
        const float2 A0 = g_A[aoff + aidx0];
        const float2 A1 = g_A[aoff + aidx1];
        const float2 A2 = g_A[aoff + aidx2];
        const float2 A3 = g_A[aoff + aidx3];

        float nr, ni;
        nr = A0.x * hr0 - A0.y * hi0 + vr.x;
        ni = A0.x * hi0 + A0.y * hr0 + vi.x;
        hr0 = nr; hi0 = ni;

        nr = A1.x * hr1 - A1.y * hi1 + vr.y;
        ni = A1.x * hi1 + A1.y * hr1 + vi.y;
        hr1 = nr; hi1 = ni;

        nr = A2.x * hr2 - A2.y * hi2 + vr.z;
        ni = A2.x * hi2 + A2.y * hr2 + vi.z;
        hr2 = nr; hi2 = ni;

        nr = A3.x * hr3 - A3.y * hi3 + vr.w;
        ni = A3.x * hi3 + A3.y * hr3 + vi.w;
        hr3 = nr; hi3 = ni;

        __stcs(&out[uoff4],             make_float4(hr0, hr1, hr2, hr3)); // real half
        __stcs(&out[(NU >> 2) + uoff4], make_float4(hi0, hi1, hi2, hi3)); // imag half
    }
}

// ---------------------------------------------------------------------------
// kernel_launch: two launches (scan via PDL), graph-capturable, no allocs.
// Inputs (metadata order): nu_rate, theta_rate, dt_seq, u_real, u_imag.
// Output: float32, shape (2, B, L, R, C, H, Wf) = 57,802,752 elements.
// ---------------------------------------------------------------------------
extern "C" void kernel_launch(void* const* d_in, const int* in_sizes, int n_in,
                              void* d_out, int out_size) {
    const float4* nu = (const float4*)d_in[0];
    const float4* th = (const float4*)d_in[1];
    const float*  dt = (const float*)d_in[2];
    const float4* ur = (const float4*)d_in[3];
    const float4* ui = (const float4*)d_in[4];
    float4* out = (float4*)d_out;

    compute_A_kernel<<<(NA / 4 + 255) / 256, 256>>>(nu, th, dt);

    constexpr int nthreads = (B * RCHW) / 4;   // 301,056
    cudaLaunchConfig_t cfg = {};
    cfg.gridDim  = dim3(nthreads / 256);       // 1176
    cfg.blockDim = dim3(256);
    cfg.stream   = 0;
    cudaLaunchAttribute attrs[1];
    attrs[0].id = cudaLaunchAttributeProgrammaticStreamSerialization;
    attrs[0].val.programmaticStreamSerializationAllowed = 1;
    cfg.attrs    = attrs;
    cfg.numAttrs = 1;
    cudaLaunchKernelEx(&cfg, scan_kernel, ur, ui, out);
}